// round 1
// baseline (speedup 1.0000x reference)
#include <cuda_runtime.h>

// Problem constants
constexpr int BSZ = 8;
constexpr int SEQ = 2048;
constexpr int DIM = 768;     // D == F == 768
constexpr int MTOT = BSZ * SEQ;   // 16384

// Static device scratch (allocation-free rule: __device__ globals)
__device__ float g_q[(size_t)MTOT * DIM];
__device__ float g_k[(size_t)MTOT * DIM];
__device__ float g_v[(size_t)MTOT * DIM];
__device__ float g_s[(size_t)BSZ * SEQ * SEQ];

// ---------------------------------------------------------------------------
// Generic fp32 SGEMM: C[M,N] = A[M,K] * B  (row-major)
//   TB=false: B is [K,N] row-major (NN)
//   TB=true : B is [N,K] row-major (NT; C = A * B^T)
// Tile: 128x128x8, 256 threads, 8x8 per thread. All dims divide tiles evenly.
// ---------------------------------------------------------------------------
template <bool TB>
__global__ __launch_bounds__(256, 2)
void sgemm_kernel(const float* __restrict__ A, const float* __restrict__ B,
                  float* __restrict__ C, int M, int N, int K,
                  long strideA, long strideB, long strideC)
{
    __shared__ float As[8][128];
    __shared__ float Bs[8][128];

    const int z = blockIdx.z;
    A += (size_t)z * strideA;
    B += (size_t)z * strideB;
    C += (size_t)z * strideC;

    const int m0 = blockIdx.y * 128;
    const int n0 = blockIdx.x * 128;
    const int tid = threadIdx.x;
    const int tx = tid & 15;   // 0..15 -> 8 output cols each
    const int ty = tid >> 4;   // 0..15 -> 8 output rows each

    // A-tile loader: 128 rows x 8 cols; each thread one float4
    const int ar = tid >> 1;          // 0..127
    const int ac = (tid & 1) * 4;     // 0 or 4
    // B-tile loader (NN): 8 rows x 128 cols; each thread one float4
    const int br = tid >> 5;          // 0..7
    const int bc = (tid & 31) * 4;    // 0..124

    float acc[8][8];
#pragma unroll
    for (int i = 0; i < 8; i++)
#pragma unroll
        for (int j = 0; j < 8; j++) acc[i][j] = 0.0f;

    for (int k0 = 0; k0 < K; k0 += 8) {
        // Load A tile (rows m0+ar, cols k0+ac..k0+ac+3), transpose into As[k][m]
        float4 av = *(const float4*)(A + (size_t)(m0 + ar) * K + k0 + ac);
        As[ac + 0][ar] = av.x;
        As[ac + 1][ar] = av.y;
        As[ac + 2][ar] = av.z;
        As[ac + 3][ar] = av.w;

        if (TB) {
            // B^T case: load rows n0+ar of B (stride K), cols k0+ac..+3
            float4 bv = *(const float4*)(B + (size_t)(n0 + ar) * K + k0 + ac);
            Bs[ac + 0][ar] = bv.x;
            Bs[ac + 1][ar] = bv.y;
            Bs[ac + 2][ar] = bv.z;
            Bs[ac + 3][ar] = bv.w;
        } else {
            // NN case: load rows k0+br of B (stride N), cols n0+bc..+3
            float4 bv = *(const float4*)(B + (size_t)(k0 + br) * N + n0 + bc);
            *(float4*)&Bs[br][bc] = bv;
        }
        __syncthreads();

#pragma unroll
        for (int kk = 0; kk < 8; kk++) {
            float a[8], b[8];
            *(float4*)(a + 0) = *(const float4*)&As[kk][ty * 8 + 0];
            *(float4*)(a + 4) = *(const float4*)&As[kk][ty * 8 + 4];
            *(float4*)(b + 0) = *(const float4*)&Bs[kk][tx * 8 + 0];
            *(float4*)(b + 4) = *(const float4*)&Bs[kk][tx * 8 + 4];
#pragma unroll
            for (int i = 0; i < 8; i++)
#pragma unroll
                for (int j = 0; j < 8; j++)
                    acc[i][j] = fmaf(a[i], b[j], acc[i][j]);
        }
        __syncthreads();
    }

    // Store 8x8 per thread as 2x float4 per row
#pragma unroll
    for (int i = 0; i < 8; i++) {
        float4 c0 = make_float4(acc[i][0], acc[i][1], acc[i][2], acc[i][3]);
        float4 c1 = make_float4(acc[i][4], acc[i][5], acc[i][6], acc[i][7]);
        float* cp = C + (size_t)(m0 + ty * 8 + i) * N + n0 + tx * 8;
        *(float4*)(cp + 0) = c0;
        *(float4*)(cp + 4) = c1;
    }
}

// ---------------------------------------------------------------------------
// Row softmax over S: 16384 rows of length SEQ=2048. One 256-thread block/row.
// ---------------------------------------------------------------------------
__global__ __launch_bounds__(256)
void softmax_kernel(float* __restrict__ S)
{
    const int row = blockIdx.x;
    float* p = S + (size_t)row * SEQ;
    const int tid = threadIdx.x;

    float v[8];
    float m = -1e30f;
#pragma unroll
    for (int i = 0; i < 8; i++) {
        v[i] = p[tid + i * 256];
        m = fmaxf(m, v[i]);
    }

    __shared__ float red[256];
    red[tid] = m;
    __syncthreads();
#pragma unroll
    for (int s = 128; s > 0; s >>= 1) {
        if (tid < s) red[tid] = fmaxf(red[tid], red[tid + s]);
        __syncthreads();
    }
    m = red[0];
    __syncthreads();

    float sum = 0.0f;
#pragma unroll
    for (int i = 0; i < 8; i++) {
        v[i] = expf(v[i] - m);
        sum += v[i];
    }
    red[tid] = sum;
    __syncthreads();
#pragma unroll
    for (int s = 128; s > 0; s >>= 1) {
        if (tid < s) red[tid] += red[tid + s];
        __syncthreads();
    }
    const float inv = 1.0f / red[0];
#pragma unroll
    for (int i = 0; i < 8; i++)
        p[tid + i * 256] = v[i] * inv;
}

// ---------------------------------------------------------------------------
// kernel_launch: 3 projection GEMMs -> batched NT scores GEMM -> softmax ->
//                batched NN output GEMM (into d_out). All default-stream,
//                graph-capturable, allocation-free.
// ---------------------------------------------------------------------------
extern "C" void kernel_launch(void* const* d_in, const int* in_sizes, int n_in,
                              void* d_out, int out_size)
{
    const float* X  = (const float*)d_in[0];
    const float* Wq = (const float*)d_in[1];
    const float* Wk = (const float*)d_in[2];
    const float* Wv = (const float*)d_in[3];
    float* out = (float*)d_out;

    float *q, *k, *v, *s;
    cudaGetSymbolAddress((void**)&q, g_q);
    cudaGetSymbolAddress((void**)&k, g_k);
    cudaGetSymbolAddress((void**)&v, g_v);
    cudaGetSymbolAddress((void**)&s, g_s);

    dim3 blk(256);

    // QKV projections: [16384,768] x [768,768]
    dim3 gp(DIM / 128, MTOT / 128, 1);
    sgemm_kernel<false><<<gp, blk>>>(X, Wq, q, MTOT, DIM, DIM, 0, 0, 0);
    sgemm_kernel<false><<<gp, blk>>>(X, Wk, k, MTOT, DIM, DIM, 0, 0, 0);
    sgemm_kernel<false><<<gp, blk>>>(X, Wv, v, MTOT, DIM, DIM, 0, 0, 0);

    // Scores: per batch S = Q * K^T  [2048,768] x [2048,768]^T
    dim3 gs(SEQ / 128, SEQ / 128, BSZ);
    sgemm_kernel<true><<<gs, blk>>>(q, k, s, SEQ, SEQ, DIM,
                                    (long)SEQ * DIM, (long)SEQ * DIM,
                                    (long)SEQ * SEQ);

    // Softmax rows
    softmax_kernel<<<BSZ * SEQ, blk>>>(s);

    // Output: per batch O = P * V  [2048,2048] x [2048,768]
    dim3 go(DIM / 128, SEQ / 128, BSZ);
    sgemm_kernel<false><<<go, blk>>>(s, v, out, SEQ, DIM, SEQ,
                                     (long)SEQ * SEQ, (long)SEQ * DIM,
                                     (long)SEQ * DIM);
}

// round 3
// speedup vs baseline: 2.4422x; 2.4422x over previous
#include <cuda_runtime.h>
#include <cuda_bf16.h>
#include <cstdint>

typedef __nv_bfloat16 bf16;

constexpr int BSZ = 8, SEQ = 2048, DIM = 768;
constexpr int MTOT = BSZ * SEQ;            // 16384

// Smem: padded rows of 40 halves (80B) per 128-row tile; 4 tiles/stage, 2 stages
constexpr int ROWB   = 80;
constexpr int TILEB  = 128 * ROWB;         // 10240
constexpr int STAGEB = 4 * TILEB;          // 40960
constexpr int SMEMSZ = 2 * STAGEB;         // 81920 (also covers 128x129 f32 epi = 66048)

// ---------------- static device scratch (allocation-free rule) --------------
__device__ bf16 g_xh[(size_t)MTOT * DIM];
__device__ bf16 g_xl[(size_t)MTOT * DIM];
__device__ bf16 g_wth[3][DIM * DIM];
__device__ bf16 g_wtl[3][DIM * DIM];
__device__ bf16 g_qh[(size_t)MTOT * DIM];
__device__ bf16 g_ql[(size_t)MTOT * DIM];
__device__ bf16 g_kh[(size_t)MTOT * DIM];
__device__ bf16 g_kl[(size_t)MTOT * DIM];
__device__ bf16 g_vth[(size_t)MTOT * DIM];   // V^T per batch: [b][768][2048]
__device__ bf16 g_vtl[(size_t)MTOT * DIM];
__device__ float g_s[(size_t)BSZ * SEQ * SEQ];
__device__ bf16 g_ph[(size_t)BSZ * SEQ * SEQ];
__device__ bf16 g_pl[(size_t)BSZ * SEQ * SEQ];

// ---------------- PTX helpers ----------------------------------------------
__device__ __forceinline__ uint32_t smem_u32(const void* p) {
    uint32_t a;
    asm("{ .reg .u64 t; cvta.to.shared.u64 t, %1; cvt.u32.u64 %0, t; }"
        : "=r"(a) : "l"(p));
    return a;
}

__device__ __forceinline__ void ldmx4(uint32_t* r, uint32_t a) {
    asm volatile("ldmatrix.sync.aligned.m8n8.x4.shared.b16 {%0,%1,%2,%3}, [%4];"
                 : "=r"(r[0]), "=r"(r[1]), "=r"(r[2]), "=r"(r[3]) : "r"(a));
}

__device__ __forceinline__ void mma_bf16(float* c, const uint32_t* a, const uint32_t* b) {
    asm volatile(
        "mma.sync.aligned.m16n8k16.row.col.f32.bf16.bf16.f32 "
        "{%0,%1,%2,%3}, {%4,%5,%6,%7}, {%8,%9}, {%0,%1,%2,%3};"
        : "+f"(c[0]), "+f"(c[1]), "+f"(c[2]), "+f"(c[3])
        : "r"(a[0]), "r"(a[1]), "r"(a[2]), "r"(a[3]), "r"(b[0]), "r"(b[1]));
}

__device__ __forceinline__ void cpasync16(uint32_t s, const void* g) {
    asm volatile("cp.async.cg.shared.global [%0], [%1], 16;" :: "r"(s), "l"(g));
}

// ---------------------------------------------------------------------------
// HMMA GEMM: C[M,N] = A * B^T, split-bf16 (3 passes: AhBh + AhBl + AlBh).
// A: [M,K] row-major hi/lo.  B: [N,K] row-major hi/lo.  fp32 accum.
// Tile 128x128xBK32, 256 threads, warp grid 4(M) x 2(N), warp tile 32x64.
// EPI 0: fp32 C (batched).  EPI 1: bf16 hi/lo C.  EPI 2: hi/lo + V->V^T.
// ---------------------------------------------------------------------------
template <int EPI>
__global__ void __launch_bounds__(256)
gemm_mma(const bf16* __restrict__ Ah, const bf16* __restrict__ Al,
         const bf16* __restrict__ Bh, const bf16* __restrict__ Bl,
         void* __restrict__ O0, void* __restrict__ O1,
         int K, long batchA, long batchB, long batchC, int ldC)
{
    extern __shared__ char smem[];
    const int tid = threadIdx.x, lane = tid & 31, wid = tid >> 5;
    const int z = blockIdx.z;
    const int m0 = blockIdx.y * 128, n0 = blockIdx.x * 128;
    const int warp_m = wid & 3, warp_n = wid >> 2;

    const char* pAh = (const char*)(Ah + (size_t)z * batchA);
    const char* pAl = (const char*)(Al + (size_t)z * batchA);
    const char* pBh = (const char*)(Bh + (size_t)z * batchB);
    const char* pBl = (const char*)(Bl + (size_t)z * batchB);

    const uint32_t sb = smem_u32(smem);
    const size_t rowbytes = (size_t)K * 2;

    float acc[2][8][4];
#pragma unroll
    for (int t = 0; t < 2; t++)
#pragma unroll
        for (int j = 0; j < 8; j++)
#pragma unroll
            for (int c = 0; c < 4; c++) acc[t][j][c] = 0.0f;

    const int nch = K >> 5;

    // loader: 512 16B chunks per array per stage; thread does chunks tid, tid+256
    const int r0c = tid >> 2, sg0 = (tid & 3) * 16;       // chunk 0: row, byte seg
    const int r1c = (tid + 256) >> 2, sg1 = sg0;          // chunk 1

#define ISSUE(kc, buf)                                                         \
    {                                                                          \
        uint32_t s0 = sb + (buf) * STAGEB;                                     \
        size_t goA0 = (size_t)(m0 + r0c) * rowbytes + (size_t)(kc) * 64 + sg0; \
        size_t goA1 = (size_t)(m0 + r1c) * rowbytes + (size_t)(kc) * 64 + sg1; \
        size_t goB0 = (size_t)(n0 + r0c) * rowbytes + (size_t)(kc) * 64 + sg0; \
        size_t goB1 = (size_t)(n0 + r1c) * rowbytes + (size_t)(kc) * 64 + sg1; \
        uint32_t so0 = r0c * ROWB + sg0, so1 = r1c * ROWB + sg1;               \
        cpasync16(s0 + 0 * TILEB + so0, pAh + goA0);                           \
        cpasync16(s0 + 0 * TILEB + so1, pAh + goA1);                           \
        cpasync16(s0 + 1 * TILEB + so0, pAl + goA0);                           \
        cpasync16(s0 + 1 * TILEB + so1, pAl + goA1);                           \
        cpasync16(s0 + 2 * TILEB + so0, pBh + goB0);                           \
        cpasync16(s0 + 2 * TILEB + so1, pBh + goB1);                           \
        cpasync16(s0 + 3 * TILEB + so0, pBl + goB0);                           \
        cpasync16(s0 + 3 * TILEB + so1, pBl + goB1);                           \
    }

    ISSUE(0, 0);
    asm volatile("cp.async.commit_group;" ::: "memory");

    for (int kc = 0; kc < nch; kc++) {
        if (kc + 1 < nch) ISSUE(kc + 1, (kc + 1) & 1);
        asm volatile("cp.async.commit_group;" ::: "memory");
        asm volatile("cp.async.wait_group 1;" ::: "memory");
        __syncthreads();

        const uint32_t sA = sb + (kc & 1) * STAGEB;
#pragma unroll
        for (int ks = 0; ks < 2; ks++) {
            const uint32_t kb = ks * 32;   // byte offset of k16 slice
            uint32_t af_h[2][4], af_l[2][4], bf_h[8][2], bf_l[8][2];

            // A frags: row = warp_m*32 + t*16 + (lane&15), col8 = (lane>>4)*8
            const uint32_t aoff = (warp_m * 32 + (lane & 15)) * ROWB + kb + (lane >> 4) * 16;
#pragma unroll
            for (int t = 0; t < 2; t++) {
                uint32_t ad = sA + aoff + t * 16 * ROWB;
                ldmx4(af_h[t], ad);
                ldmx4(af_l[t], ad + TILEB);
            }
            // B frags: x4 covers n-tile pair; row = warp_n*64 + jp*16 + (lane>>4)*8 + (lane&7)
            const uint32_t boff = (warp_n * 64 + (lane >> 4) * 8 + (lane & 7)) * ROWB +
                                  kb + ((lane >> 3) & 1) * 16;
#pragma unroll
            for (int jp = 0; jp < 4; jp++) {
                uint32_t bd = sA + 2 * TILEB + boff + jp * 16 * ROWB;
                uint32_t r4[4];
                ldmx4(r4, bd);
                bf_h[jp * 2 + 0][0] = r4[0]; bf_h[jp * 2 + 0][1] = r4[1];
                bf_h[jp * 2 + 1][0] = r4[2]; bf_h[jp * 2 + 1][1] = r4[3];
                ldmx4(r4, bd + TILEB);
                bf_l[jp * 2 + 0][0] = r4[0]; bf_l[jp * 2 + 0][1] = r4[1];
                bf_l[jp * 2 + 1][0] = r4[2]; bf_l[jp * 2 + 1][1] = r4[3];
            }

            // 3 passes: AhBh, AhBl, AlBh (pass-outermost for acc ILP)
#pragma unroll
            for (int t = 0; t < 2; t++)
#pragma unroll
                for (int j = 0; j < 8; j++) mma_bf16(acc[t][j], af_h[t], bf_h[j]);
#pragma unroll
            for (int t = 0; t < 2; t++)
#pragma unroll
                for (int j = 0; j < 8; j++) mma_bf16(acc[t][j], af_h[t], bf_l[j]);
#pragma unroll
            for (int t = 0; t < 2; t++)
#pragma unroll
                for (int j = 0; j < 8; j++) mma_bf16(acc[t][j], af_l[t], bf_h[j]);
        }
        __syncthreads();
    }
#undef ISSUE

    // ---------------- epilogue ----------------
    const int rbase = warp_m * 32 + (lane >> 2);
    const int cbase = warp_n * 64 + (lane & 3) * 2;

    if (EPI == 0) {
        float* C = (float*)O0 + (size_t)z * batchC;
#pragma unroll
        for (int t = 0; t < 2; t++)
#pragma unroll
            for (int j = 0; j < 8; j++) {
                int rr = m0 + rbase + t * 16;
                int cc = n0 + cbase + j * 8;
                *(float2*)(C + (size_t)rr * ldC + cc) =
                    make_float2(acc[t][j][0], acc[t][j][1]);
                *(float2*)(C + (size_t)(rr + 8) * ldC + cc) =
                    make_float2(acc[t][j][2], acc[t][j][3]);
            }
    } else if (EPI == 1) {
        bf16* Oh = (bf16*)O0;
        bf16* Ol = (bf16*)O1;
#pragma unroll
        for (int t = 0; t < 2; t++)
#pragma unroll
            for (int j = 0; j < 8; j++)
#pragma unroll
                for (int h = 0; h < 2; h++) {
                    int rr = m0 + rbase + t * 16 + h * 8;
                    int cc = n0 + cbase + j * 8;
                    float x0 = acc[t][j][h * 2 + 0], x1 = acc[t][j][h * 2 + 1];
                    bf16 h0 = __float2bfloat16(x0), h1 = __float2bfloat16(x1);
                    bf16 l0 = __float2bfloat16(x0 - __bfloat162float(h0));
                    bf16 l1 = __float2bfloat16(x1 - __bfloat162float(h1));
                    __nv_bfloat162 hp; hp.x = h0; hp.y = h1;
                    __nv_bfloat162 lp; lp.x = l0; lp.y = l1;
                    *(__nv_bfloat162*)(Oh + (size_t)rr * ldC + cc) = hp;
                    *(__nv_bfloat162*)(Ol + (size_t)rr * ldC + cc) = lp;
                }
    } else {
        // EPI 2: stage fp32 tile in smem [128][129], then transposed hi/lo store
        float* st = (float*)smem;
#pragma unroll
        for (int t = 0; t < 2; t++)
#pragma unroll
            for (int j = 0; j < 8; j++)
#pragma unroll
                for (int h = 0; h < 2; h++) {
                    int rr = rbase + t * 16 + h * 8;
                    int cc = cbase + j * 8;
                    st[rr * 129 + cc + 0] = acc[t][j][h * 2 + 0];
                    st[rr * 129 + cc + 1] = acc[t][j][h * 2 + 1];
                }
        __syncthreads();
        bf16* Oh = (bf16*)O0;
        bf16* Ol = (bf16*)O1;
        for (int idx = tid; idx < 128 * 128; idx += 256) {
            int nl = idx >> 7, ml = idx & 127;
            int mg = m0 + ml;
            int b = mg >> 11, mloc = mg & 2047;
            float x = st[ml * 129 + nl];
            bf16 h = __float2bfloat16(x);
            bf16 l = __float2bfloat16(x - __bfloat162float(h));
            size_t o = (size_t)b * DIM * SEQ + (size_t)(n0 + nl) * SEQ + mloc;
            Oh[o] = h;
            Ol[o] = l;
        }
    }
}

// ---------------- prep kernels ----------------------------------------------
__global__ void split_kernel(const float* __restrict__ X,
                             bf16* __restrict__ H, bf16* __restrict__ L, int n)
{
    int i = blockIdx.x * 256 + threadIdx.x;
    if (i < n) {
        float x = X[i];
        bf16 h = __float2bfloat16(x);
        H[i] = h;
        L[i] = __float2bfloat16(x - __bfloat162float(h));
    }
}

__global__ void wsplit_kernel(const float* __restrict__ W,
                              bf16* __restrict__ TH, bf16* __restrict__ TL)
{
    int i = blockIdx.x * 256 + threadIdx.x;   // out idx f*DIM + d
    int f = i / DIM, d = i % DIM;
    float x = W[d * DIM + f];
    bf16 h = __float2bfloat16(x);
    TH[i] = h;
    TL[i] = __float2bfloat16(x - __bfloat162float(h));
}

// ---------------- softmax: S fp32 -> P split bf16 ---------------------------
__global__ void __launch_bounds__(256)
softmax_kernel(const float* __restrict__ S,
               bf16* __restrict__ Ph, bf16* __restrict__ Pl)
{
    const int row = blockIdx.x;
    const float* p = S + (size_t)row * SEQ;
    const int tid = threadIdx.x;

    float v[8];
    float m = -1e30f;
#pragma unroll
    for (int i = 0; i < 8; i++) {
        v[i] = p[tid + i * 256];
        m = fmaxf(m, v[i]);
    }

    __shared__ float red[256];
    red[tid] = m;
    __syncthreads();
#pragma unroll
    for (int s = 128; s > 0; s >>= 1) {
        if (tid < s) red[tid] = fmaxf(red[tid], red[tid + s]);
        __syncthreads();
    }
    m = red[0];
    __syncthreads();

    float sum = 0.0f;
#pragma unroll
    for (int i = 0; i < 8; i++) {
        v[i] = expf(v[i] - m);
        sum += v[i];
    }
    red[tid] = sum;
    __syncthreads();
#pragma unroll
    for (int s = 128; s > 0; s >>= 1) {
        if (tid < s) red[tid] += red[tid + s];
        __syncthreads();
    }
    const float inv = 1.0f / red[0];
#pragma unroll
    for (int i = 0; i < 8; i++) {
        float pr = v[i] * inv;
        bf16 h = __float2bfloat16(pr);
        size_t o = (size_t)row * SEQ + tid + i * 256;
        Ph[o] = h;
        Pl[o] = __float2bfloat16(pr - __bfloat162float(h));
    }
}

// ---------------------------------------------------------------------------
extern "C" void kernel_launch(void* const* d_in, const int* in_sizes, int n_in,
                              void* d_out, int out_size)
{
    const float* X  = (const float*)d_in[0];
    const float* Wq = (const float*)d_in[1];
    const float* Wk = (const float*)d_in[2];
    const float* Wv = (const float*)d_in[3];
    float* out = (float*)d_out;

    bf16 *xh, *xl, *wth, *wtl, *qh, *ql, *kh, *kl, *vth, *vtl, *ph, *pl;
    float* s;
    cudaGetSymbolAddress((void**)&xh, g_xh);
    cudaGetSymbolAddress((void**)&xl, g_xl);
    cudaGetSymbolAddress((void**)&wth, g_wth);
    cudaGetSymbolAddress((void**)&wtl, g_wtl);
    cudaGetSymbolAddress((void**)&qh, g_qh);
    cudaGetSymbolAddress((void**)&ql, g_ql);
    cudaGetSymbolAddress((void**)&kh, g_kh);
    cudaGetSymbolAddress((void**)&kl, g_kl);
    cudaGetSymbolAddress((void**)&vth, g_vth);
    cudaGetSymbolAddress((void**)&vtl, g_vtl);
    cudaGetSymbolAddress((void**)&ph, g_ph);
    cudaGetSymbolAddress((void**)&pl, g_pl);
    cudaGetSymbolAddress((void**)&s, g_s);

    cudaFuncSetAttribute(gemm_mma<0>, cudaFuncAttributeMaxDynamicSharedMemorySize, SMEMSZ);
    cudaFuncSetAttribute(gemm_mma<1>, cudaFuncAttributeMaxDynamicSharedMemorySize, SMEMSZ);
    cudaFuncSetAttribute(gemm_mma<2>, cudaFuncAttributeMaxDynamicSharedMemorySize, SMEMSZ);

    const int nx = MTOT * DIM;
    split_kernel<<<nx / 256, 256>>>(X, xh, xl, nx);
    wsplit_kernel<<<(DIM * DIM) / 256, 256>>>(Wq, wth + 0 * DIM * DIM, wtl + 0 * DIM * DIM);
    wsplit_kernel<<<(DIM * DIM) / 256, 256>>>(Wk, wth + 1 * DIM * DIM, wtl + 1 * DIM * DIM);
    wsplit_kernel<<<(DIM * DIM) / 256, 256>>>(Wv, wth + 2 * DIM * DIM, wtl + 2 * DIM * DIM);

    // Projections: [16384,768] = X * (W^T)^T
    dim3 gp(DIM / 128, MTOT / 128, 1);
    gemm_mma<1><<<gp, 256, SMEMSZ>>>(xh, xl, wth + 0 * DIM * DIM, wtl + 0 * DIM * DIM,
                                     qh, ql, DIM, 0, 0, 0, DIM);
    gemm_mma<1><<<gp, 256, SMEMSZ>>>(xh, xl, wth + 1 * DIM * DIM, wtl + 1 * DIM * DIM,
                                     kh, kl, DIM, 0, 0, 0, DIM);
    gemm_mma<2><<<gp, 256, SMEMSZ>>>(xh, xl, wth + 2 * DIM * DIM, wtl + 2 * DIM * DIM,
                                     vth, vtl, DIM, 0, 0, 0, 0);

    // Scores: per batch S = Q * K^T, [2048,2048], K=768
    dim3 gs(SEQ / 128, SEQ / 128, BSZ);
    gemm_mma<0><<<gs, 256, SMEMSZ>>>(qh, ql, kh, kl, s, nullptr, DIM,
                                     (long)SEQ * DIM, (long)SEQ * DIM,
                                     (long)SEQ * SEQ, SEQ);

    softmax_kernel<<<BSZ * SEQ, 256>>>(s, ph, pl);

    // Out: per batch O = P * (V^T)^T, [2048,768], K=2048
    dim3 go(DIM / 128, SEQ / 128, BSZ);
    gemm_mma<0><<<go, 256, SMEMSZ>>>(ph, pl, vth, vtl, out, nullptr, SEQ,
                                     (long)SEQ * SEQ, (long)DIM * SEQ,
                                     (long)SEQ * DIM, DIM);
}

// round 4
// speedup vs baseline: 2.7368x; 1.1206x over previous
#include <cuda_runtime.h>
#include <cuda_bf16.h>
#include <cstdint>

typedef __nv_bfloat16 bf16;

constexpr int BSZ = 8, SEQ = 2048, DIM = 768;
constexpr int MTOT = BSZ * SEQ;            // 16384

// Smem: padded rows of 40 halves (80B) per 128-row tile; 4 tiles/stage, 2 stages
constexpr int ROWB   = 80;
constexpr int TILEB  = 128 * ROWB;         // 10240
constexpr int STAGEB = 4 * TILEB;          // 40960
constexpr int SMEMSZ = 2 * STAGEB;         // 81920 (covers 128x129 f32 epi = 66048)

// ---------------- static device scratch (allocation-free rule) --------------
__device__ bf16 g_xh[(size_t)MTOT * DIM];
__device__ bf16 g_xl[(size_t)MTOT * DIM];
__device__ bf16 g_wth[3][DIM * DIM];
__device__ bf16 g_wtl[3][DIM * DIM];
__device__ bf16 g_qh[(size_t)MTOT * DIM];
__device__ bf16 g_ql[(size_t)MTOT * DIM];
__device__ bf16 g_kh[(size_t)MTOT * DIM];
__device__ bf16 g_kl[(size_t)MTOT * DIM];
__device__ bf16 g_vth[(size_t)MTOT * DIM];   // V^T per batch: [b][768][2048]
__device__ bf16 g_vtl[(size_t)MTOT * DIM];
__device__ float g_s[(size_t)BSZ * SEQ * SEQ];
__device__ bf16 g_ph[(size_t)BSZ * SEQ * SEQ];
__device__ bf16 g_pl[(size_t)BSZ * SEQ * SEQ];

// ---------------- PTX helpers ----------------------------------------------
__device__ __forceinline__ uint32_t smem_u32(const void* p) {
    uint32_t a;
    asm("{ .reg .u64 t; cvta.to.shared.u64 t, %1; cvt.u32.u64 %0, t; }"
        : "=r"(a) : "l"(p));
    return a;
}

__device__ __forceinline__ void ldmx4(uint32_t* r, uint32_t a) {
    asm volatile("ldmatrix.sync.aligned.m8n8.x4.shared.b16 {%0,%1,%2,%3}, [%4];"
                 : "=r"(r[0]), "=r"(r[1]), "=r"(r[2]), "=r"(r[3]) : "r"(a));
}

__device__ __forceinline__ void mma_bf16(float* c, const uint32_t* a, const uint32_t* b) {
    asm volatile(
        "mma.sync.aligned.m16n8k16.row.col.f32.bf16.bf16.f32 "
        "{%0,%1,%2,%3}, {%4,%5,%6,%7}, {%8,%9}, {%0,%1,%2,%3};"
        : "+f"(c[0]), "+f"(c[1]), "+f"(c[2]), "+f"(c[3])
        : "r"(a[0]), "r"(a[1]), "r"(a[2]), "r"(a[3]), "r"(b[0]), "r"(b[1]));
}

__device__ __forceinline__ void cpasync16(uint32_t s, const void* g) {
    asm volatile("cp.async.cg.shared.global [%0], [%1], 16;" :: "r"(s), "l"(g));
}

// ---------------------------------------------------------------------------
// HMMA GEMM: C[M,N] = A * B^T, split-bf16 (3 passes: AhBh + AhBl + AlBh).
// A: [M,K] row-major hi/lo.  B: [N,K] row-major hi/lo.  fp32 accum.
// Tile 128x128xBK32, 256 threads, warp grid 4(M) x 2(N), warp tile 32x64.
// 2 CTAs/SM (reg-lean inner loop: B frags loaded per column-pair).
// EPI 0: fp32 C (batched).  EPI 1: bf16 hi/lo C.  EPI 2: hi/lo + V->V^T.
// ---------------------------------------------------------------------------
template <int EPI>
__global__ void __launch_bounds__(256, 2)
gemm_mma(const bf16* __restrict__ Ah, const bf16* __restrict__ Al,
         const bf16* __restrict__ Bh, const bf16* __restrict__ Bl,
         void* __restrict__ O0, void* __restrict__ O1,
         int K, long batchA, long batchB, long batchC, int ldC)
{
    extern __shared__ char smem[];
    const int tid = threadIdx.x, lane = tid & 31, wid = tid >> 5;
    const int z = blockIdx.z;
    const int m0 = blockIdx.y * 128, n0 = blockIdx.x * 128;
    const int warp_m = wid & 3, warp_n = wid >> 2;

    const char* pAh = (const char*)(Ah + (size_t)z * batchA);
    const char* pAl = (const char*)(Al + (size_t)z * batchA);
    const char* pBh = (const char*)(Bh + (size_t)z * batchB);
    const char* pBl = (const char*)(Bl + (size_t)z * batchB);

    const uint32_t sb = smem_u32(smem);
    const uint32_t rowbytes = (uint32_t)K * 2;

    float acc[2][8][4];
#pragma unroll
    for (int t = 0; t < 2; t++)
#pragma unroll
        for (int j = 0; j < 8; j++)
#pragma unroll
            for (int c = 0; c < 4; c++) acc[t][j][c] = 0.0f;

    const int nch = K >> 5;

    // loader: 512 16B chunks per array per stage; thread does chunks tid, tid+256
    const int r0c = tid >> 2, sg0 = (tid & 3) * 16;
    const int r1c = (tid + 256) >> 2;

#define ISSUE(kc, buf)                                                          \
    {                                                                           \
        uint32_t s0 = sb + (buf) * STAGEB;                                      \
        size_t goA0 = (size_t)(m0 + r0c) * rowbytes + (size_t)(kc) * 64 + sg0;  \
        size_t goA1 = (size_t)(m0 + r1c) * rowbytes + (size_t)(kc) * 64 + sg0;  \
        size_t goB0 = (size_t)(n0 + r0c) * rowbytes + (size_t)(kc) * 64 + sg0;  \
        size_t goB1 = (size_t)(n0 + r1c) * rowbytes + (size_t)(kc) * 64 + sg0;  \
        uint32_t so0 = r0c * ROWB + sg0, so1 = r1c * ROWB + sg0;                \
        cpasync16(s0 + 0 * TILEB + so0, pAh + goA0);                            \
        cpasync16(s0 + 0 * TILEB + so1, pAh + goA1);                            \
        cpasync16(s0 + 1 * TILEB + so0, pAl + goA0);                            \
        cpasync16(s0 + 1 * TILEB + so1, pAl + goA1);                            \
        cpasync16(s0 + 2 * TILEB + so0, pBh + goB0);                            \
        cpasync16(s0 + 2 * TILEB + so1, pBh + goB1);                            \
        cpasync16(s0 + 3 * TILEB + so0, pBl + goB0);                            \
        cpasync16(s0 + 3 * TILEB + so1, pBl + goB1);                            \
    }

    ISSUE(0, 0);
    asm volatile("cp.async.commit_group;" ::: "memory");

    for (int kc = 0; kc < nch; kc++) {
        if (kc + 1 < nch) ISSUE(kc + 1, (kc + 1) & 1);
        asm volatile("cp.async.commit_group;" ::: "memory");
        asm volatile("cp.async.wait_group 1;" ::: "memory");
        __syncthreads();

        const uint32_t sA = sb + (kc & 1) * STAGEB;
#pragma unroll
        for (int ks = 0; ks < 2; ks++) {
            const uint32_t kb = ks * 32;   // byte offset of k16 slice
            uint32_t af_h[2][4], af_l[2][4];

            // A frags: row = warp_m*32 + t*16 + (lane&15), col8 = (lane>>4)*8
            const uint32_t aoff = (warp_m * 32 + (lane & 15)) * ROWB + kb + (lane >> 4) * 16;
#pragma unroll
            for (int t = 0; t < 2; t++) {
                uint32_t ad = sA + aoff + t * 16 * ROWB;
                ldmx4(af_h[t], ad);
                ldmx4(af_l[t], ad + TILEB);
            }

            // B frags loaded per column-pair (keeps live regs low -> 2 CTAs/SM)
            const uint32_t boff = (warp_n * 64 + (lane >> 4) * 8 + (lane & 7)) * ROWB +
                                  kb + ((lane >> 3) & 1) * 16;
#pragma unroll
            for (int jp = 0; jp < 4; jp++) {
                uint32_t bd = sA + 2 * TILEB + boff + jp * 16 * ROWB;
                uint32_t rh[4], rl[4];
                ldmx4(rh, bd);
                ldmx4(rl, bd + TILEB);
                const int j0 = jp * 2, j1 = jp * 2 + 1;
                // product-type outer: RAW distance 4 MMAs per accumulator
#pragma unroll
                for (int t = 0; t < 2; t++) {
                    mma_bf16(acc[t][j0], af_h[t], rh + 0);
                    mma_bf16(acc[t][j1], af_h[t], rh + 2);
                }
#pragma unroll
                for (int t = 0; t < 2; t++) {
                    mma_bf16(acc[t][j0], af_h[t], rl + 0);
                    mma_bf16(acc[t][j1], af_h[t], rl + 2);
                }
#pragma unroll
                for (int t = 0; t < 2; t++) {
                    mma_bf16(acc[t][j0], af_l[t], rh + 0);
                    mma_bf16(acc[t][j1], af_l[t], rh + 2);
                }
            }
        }
        __syncthreads();
    }
#undef ISSUE

    // ---------------- epilogue ----------------
    const int rbase = warp_m * 32 + (lane >> 2);
    const int cbase = warp_n * 64 + (lane & 3) * 2;

    if (EPI == 0) {
        float* C = (float*)O0 + (size_t)z * batchC;
#pragma unroll
        for (int t = 0; t < 2; t++)
#pragma unroll
            for (int j = 0; j < 8; j++) {
                int rr = m0 + rbase + t * 16;
                int cc = n0 + cbase + j * 8;
                *(float2*)(C + (size_t)rr * ldC + cc) =
                    make_float2(acc[t][j][0], acc[t][j][1]);
                *(float2*)(C + (size_t)(rr + 8) * ldC + cc) =
                    make_float2(acc[t][j][2], acc[t][j][3]);
            }
    } else if (EPI == 1) {
        bf16* Oh = (bf16*)O0;
        bf16* Ol = (bf16*)O1;
#pragma unroll
        for (int t = 0; t < 2; t++)
#pragma unroll
            for (int j = 0; j < 8; j++)
#pragma unroll
                for (int h = 0; h < 2; h++) {
                    int rr = m0 + rbase + t * 16 + h * 8;
                    int cc = n0 + cbase + j * 8;
                    float x0 = acc[t][j][h * 2 + 0], x1 = acc[t][j][h * 2 + 1];
                    bf16 h0 = __float2bfloat16(x0), h1 = __float2bfloat16(x1);
                    bf16 l0 = __float2bfloat16(x0 - __bfloat162float(h0));
                    bf16 l1 = __float2bfloat16(x1 - __bfloat162float(h1));
                    __nv_bfloat162 hp; hp.x = h0; hp.y = h1;
                    __nv_bfloat162 lp; lp.x = l0; lp.y = l1;
                    *(__nv_bfloat162*)(Oh + (size_t)rr * ldC + cc) = hp;
                    *(__nv_bfloat162*)(Ol + (size_t)rr * ldC + cc) = lp;
                }
    } else {
        // EPI 2: stage fp32 tile in smem [128][129], then transposed hi/lo store
        float* st = (float*)smem;
#pragma unroll
        for (int t = 0; t < 2; t++)
#pragma unroll
            for (int j = 0; j < 8; j++)
#pragma unroll
                for (int h = 0; h < 2; h++) {
                    int rr = rbase + t * 16 + h * 8;
                    int cc = cbase + j * 8;
                    st[rr * 129 + cc + 0] = acc[t][j][h * 2 + 0];
                    st[rr * 129 + cc + 1] = acc[t][j][h * 2 + 1];
                }
        __syncthreads();
        bf16* Oh = (bf16*)O0;
        bf16* Ol = (bf16*)O1;
        for (int idx = tid; idx < 128 * 128; idx += 256) {
            int nl = idx >> 7, ml = idx & 127;
            int mg = m0 + ml;
            int b = mg >> 11, mloc = mg & 2047;
            float x = st[ml * 129 + nl];
            bf16 h = __float2bfloat16(x);
            bf16 l = __float2bfloat16(x - __bfloat162float(h));
            size_t o = (size_t)b * DIM * SEQ + (size_t)(n0 + nl) * SEQ + mloc;
            Oh[o] = h;
            Ol[o] = l;
        }
    }
}

// ---------------- prep kernels ----------------------------------------------
__global__ void split_kernel(const float* __restrict__ X,
                             bf16* __restrict__ H, bf16* __restrict__ L, int n)
{
    int i = blockIdx.x * 256 + threadIdx.x;
    if (i < n) {
        float x = X[i];
        bf16 h = __float2bfloat16(x);
        H[i] = h;
        L[i] = __float2bfloat16(x - __bfloat162float(h));
    }
}

__global__ void wsplit_kernel(const float* __restrict__ W,
                              bf16* __restrict__ TH, bf16* __restrict__ TL)
{
    int i = blockIdx.x * 256 + threadIdx.x;   // out idx f*DIM + d
    int f = i / DIM, d = i % DIM;
    float x = W[d * DIM + f];
    bf16 h = __float2bfloat16(x);
    TH[i] = h;
    TL[i] = __float2bfloat16(x - __bfloat162float(h));
}

// ---------------- softmax: S fp32 -> P split bf16 ---------------------------
__global__ void __launch_bounds__(256)
softmax_kernel(const float* __restrict__ S,
               bf16* __restrict__ Ph, bf16* __restrict__ Pl)
{
    const int row = blockIdx.x;
    const float* p = S + (size_t)row * SEQ;
    const int tid = threadIdx.x;

    float v[8];
    float m = -1e30f;
#pragma unroll
    for (int i = 0; i < 8; i++) {
        v[i] = p[tid + i * 256];
        m = fmaxf(m, v[i]);
    }

    __shared__ float red[256];
    red[tid] = m;
    __syncthreads();
#pragma unroll
    for (int s = 128; s > 0; s >>= 1) {
        if (tid < s) red[tid] = fmaxf(red[tid], red[tid + s]);
        __syncthreads();
    }
    m = red[0];
    __syncthreads();

    float sum = 0.0f;
#pragma unroll
    for (int i = 0; i < 8; i++) {
        v[i] = expf(v[i] - m);
        sum += v[i];
    }
    red[tid] = sum;
    __syncthreads();
#pragma unroll
    for (int s = 128; s > 0; s >>= 1) {
        if (tid < s) red[tid] += red[tid + s];
        __syncthreads();
    }
    const float inv = 1.0f / red[0];
#pragma unroll
    for (int i = 0; i < 8; i++) {
        float pr = v[i] * inv;
        bf16 h = __float2bfloat16(pr);
        size_t o = (size_t)row * SEQ + tid + i * 256;
        Ph[o] = h;
        Pl[o] = __float2bfloat16(pr - __bfloat162float(h));
    }
}

// ---------------------------------------------------------------------------
extern "C" void kernel_launch(void* const* d_in, const int* in_sizes, int n_in,
                              void* d_out, int out_size)
{
    const float* X  = (const float*)d_in[0];
    const float* Wq = (const float*)d_in[1];
    const float* Wk = (const float*)d_in[2];
    const float* Wv = (const float*)d_in[3];
    float* out = (float*)d_out;

    bf16 *xh, *xl, *wth, *wtl, *qh, *ql, *kh, *kl, *vth, *vtl, *ph, *pl;
    float* s;
    cudaGetSymbolAddress((void**)&xh, g_xh);
    cudaGetSymbolAddress((void**)&xl, g_xl);
    cudaGetSymbolAddress((void**)&wth, g_wth);
    cudaGetSymbolAddress((void**)&wtl, g_wtl);
    cudaGetSymbolAddress((void**)&qh, g_qh);
    cudaGetSymbolAddress((void**)&ql, g_ql);
    cudaGetSymbolAddress((void**)&kh, g_kh);
    cudaGetSymbolAddress((void**)&kl, g_kl);
    cudaGetSymbolAddress((void**)&vth, g_vth);
    cudaGetSymbolAddress((void**)&vtl, g_vtl);
    cudaGetSymbolAddress((void**)&ph, g_ph);
    cudaGetSymbolAddress((void**)&pl, g_pl);
    cudaGetSymbolAddress((void**)&s, g_s);

    cudaFuncSetAttribute(gemm_mma<0>, cudaFuncAttributeMaxDynamicSharedMemorySize, SMEMSZ);
    cudaFuncSetAttribute(gemm_mma<1>, cudaFuncAttributeMaxDynamicSharedMemorySize, SMEMSZ);
    cudaFuncSetAttribute(gemm_mma<2>, cudaFuncAttributeMaxDynamicSharedMemorySize, SMEMSZ);

    const int nx = MTOT * DIM;
    split_kernel<<<nx / 256, 256>>>(X, xh, xl, nx);
    wsplit_kernel<<<(DIM * DIM) / 256, 256>>>(Wq, wth + 0 * DIM * DIM, wtl + 0 * DIM * DIM);
    wsplit_kernel<<<(DIM * DIM) / 256, 256>>>(Wk, wth + 1 * DIM * DIM, wtl + 1 * DIM * DIM);
    wsplit_kernel<<<(DIM * DIM) / 256, 256>>>(Wv, wth + 2 * DIM * DIM, wtl + 2 * DIM * DIM);

    // Projections: [16384,768] = X * (W^T)^T
    dim3 gp(DIM / 128, MTOT / 128, 1);
    gemm_mma<1><<<gp, 256, SMEMSZ>>>(xh, xl, wth + 0 * DIM * DIM, wtl + 0 * DIM * DIM,
                                     qh, ql, DIM, 0, 0, 0, DIM);
    gemm_mma<1><<<gp, 256, SMEMSZ>>>(xh, xl, wth + 1 * DIM * DIM, wtl + 1 * DIM * DIM,
                                     kh, kl, DIM, 0, 0, 0, DIM);
    gemm_mma<2><<<gp, 256, SMEMSZ>>>(xh, xl, wth + 2 * DIM * DIM, wtl + 2 * DIM * DIM,
                                     vth, vtl, DIM, 0, 0, 0, 0);

    // Scores: per batch S = Q * K^T, [2048,2048], K=768
    dim3 gs(SEQ / 128, SEQ / 128, BSZ);
    gemm_mma<0><<<gs, 256, SMEMSZ>>>(qh, ql, kh, kl, s, nullptr, DIM,
                                     (long)SEQ * DIM, (long)SEQ * DIM,
                                     (long)SEQ * SEQ, SEQ);

    softmax_kernel<<<BSZ * SEQ, 256>>>(s, ph, pl);

    // Out: per batch O = P * (V^T)^T, [2048,768], K=2048
    dim3 go(DIM / 128, SEQ / 128, BSZ);
    gemm_mma<0><<<go, 256, SMEMSZ>>>(ph, pl, vth, vtl, out, nullptr, SEQ,
                                     (long)SEQ * SEQ, (long)DIM * SEQ,
                                     (long)SEQ * DIM, DIM);
}